// round 13
// baseline (speedup 1.0000x reference)
#include <cuda_runtime.h>
#include <cstdint>

// ---------------- problem constants ----------------
#define WRANKS 8
#define MDIM   4096
#define NDIM   4096
#define KDIM   1792

// ---------------- tile config ----------------
#define BM 128
#define BN 128
#define BK 32
#define NTHREADS 256
#define STAGES 3
#define TOTAL_STAGES ((WRANKS * KDIM) / BK)   // 448
#define STAGES_PER_RANK (KDIM / BK)           // 56

// smem row pitch in words: 36 -> 144B rows; 16B chunks aligned; ldmatrix rows
// stride 4 words mod 32 -> each 8-row matrix tiles all 32 banks (conflict-free)
#define SSTRIDE 36
#define TILE_WORDS (BM * SSTRIDE)             // 4608
#define STAGE_WORDS (2 * TILE_WORDS)
#define DYN_SMEM (STAGES * STAGE_WORDS * 4)   // 110592 B -> 2 CTAs/SM

// ---------------- tf32 scratch (pre-rounded operands) ----------------
__device__ __align__(16) unsigned g_a_tf32[(size_t)WRANKS * MDIM * KDIM];
__device__ __align__(16) unsigned g_b_tf32[(size_t)WRANKS * NDIM * KDIM];

// ---------------- helpers ----------------
__device__ __forceinline__ unsigned f2tf32(float x) {
    unsigned r;
    asm("cvt.rna.tf32.f32 %0, %1;" : "=r"(r) : "f"(x));
    return r;
}

__device__ __forceinline__ uint32_t smem_to_u32(const void* p) {
    uint32_t a;
    asm("{ .reg .u64 t; cvta.to.shared.u64 t, %1; cvt.u32.u64 %0, t; }" : "=r"(a) : "l"(p));
    return a;
}

__device__ __forceinline__ void cp_async16(uint32_t dst, const void* src) {
    asm volatile("cp.async.cg.shared.global [%0], [%1], 16;" :: "r"(dst), "l"(src));
}
#define CP_COMMIT() asm volatile("cp.async.commit_group;" ::: "memory")
#define CP_WAIT(n)  asm volatile("cp.async.wait_group %0;" :: "n"(n) : "memory")

// ldmatrix: 4 independent dst regs, canonical mma.sync fragment layout
__device__ __forceinline__ void ldsm_x4(unsigned& r0, unsigned& r1, unsigned& r2, unsigned& r3,
                                        uint32_t addr) {
    asm volatile("ldmatrix.sync.aligned.m8n8.x4.shared.b16 {%0,%1,%2,%3}, [%4];"
                 : "=r"(r0), "=r"(r1), "=r"(r2), "=r"(r3) : "r"(addr));
}

__device__ __forceinline__ void mma_tf32_m16n8k8(float c[4], const unsigned a[4],
                                                 unsigned b0, unsigned b1) {
    asm volatile(
        "mma.sync.aligned.m16n8k8.row.col.f32.tf32.tf32.f32 "
        "{%0,%1,%2,%3}, {%4,%5,%6,%7}, {%8,%9}, {%0,%1,%2,%3};\n"
        : "+f"(c[0]), "+f"(c[1]), "+f"(c[2]), "+f"(c[3])
        : "r"(a[0]), "r"(a[1]), "r"(a[2]), "r"(a[3]), "r"(b0), "r"(b1));
}

// ---------------- pass 1: fp32 -> tf32(RNA) bits ----------------
__global__ void __launch_bounds__(256) convert_tf32_kernel(
    const float4* __restrict__ a, const float4* __restrict__ b,
    uint4* __restrict__ oa, uint4* __restrict__ ob)
{
    const size_t n4 = (size_t)WRANKS * MDIM * KDIM / 4;
    size_t stride = (size_t)gridDim.x * blockDim.x;
    for (size_t i = (size_t)blockIdx.x * blockDim.x + threadIdx.x; i < n4; i += stride) {
        float4 va = a[i];
        uint4 ua = { f2tf32(va.x), f2tf32(va.y), f2tf32(va.z), f2tf32(va.w) };
        oa[i] = ua;
        float4 vb = b[i];
        uint4 ub = { f2tf32(vb.x), f2tf32(vb.y), f2tf32(vb.z), f2tf32(vb.w) };
        ob[i] = ub;
    }
}

// ---------------- pass 2: pipelined tf32 GEMM, warp-staggered k-steps ----------------
extern __shared__ unsigned dsm[];

__global__ void __launch_bounds__(NTHREADS, 2)
gemm_ar_tf32_pipe(const unsigned* __restrict__ ga,   // [W, M, K] tf32 bits
                  const unsigned* __restrict__ gb,   // [W, N, K] tf32 bits
                  float* __restrict__ out)           // [M, N]
{
    const int tid  = threadIdx.x;
    const int warp = tid >> 5;
    const int lane = tid & 31;
    const int g    = lane >> 2;
    const int t    = lane & 3;

    // grid swizzle: 8-wide N-tile groups (B stays L2-resident across M sweep)
    const int GW = 8;
    const int MT = MDIM / BM;  // 32
    int gid   = blockIdx.x;
    int group = gid / (GW * MT);
    int rem   = gid % (GW * MT);
    int mt    = rem / GW;
    int nt    = group * GW + (rem % GW);
    const int m0 = mt * BM;
    const int n0 = nt * BN;

    const int wm = warp & 3;   // 4x2 warps, each 32(M) x 64(N)
    const int wn = warp >> 2;

    const int row0  = tid >> 3;
    const int chunk = tid & 7;

    const uint32_t smem_u = smem_to_u32(dsm);

    // ldmatrix per-lane byte offsets (within a tile)
    uint32_t a_off[2], b_off[4];
    {
        const int arow = lane & 15;
        const int acol = (lane >> 4) * 4;
        #pragma unroll
        for (int im = 0; im < 2; im++)
            a_off[im] = ((wm * 32 + im * 16 + arow) * SSTRIDE + acol) * 4;
        const int brow = (lane & 7) + ((lane >> 4) << 3);
        const int bcol = ((lane >> 3) & 1) * 4;
        #pragma unroll
        for (int p = 0; p < 4; p++)
            b_off[p] = ((wn * 64 + p * 16 + brow) * SSTRIDE + bcol) * 4 + TILE_WORDS * 4;
    }

    float acc[2][8][4];
    #pragma unroll
    for (int im = 0; im < 2; im++)
        #pragma unroll
        for (int in = 0; in < 8; in++)
            #pragma unroll
            for (int j = 0; j < 4; j++)
                acc[im][in][j] = 0.0f;

    auto issue = [&](int s, int buf) {
        const int r  = s / STAGES_PER_RANK;
        const int kk = (s % STAGES_PER_RANK) * BK;
        const unsigned* Ab = ga + ((size_t)r * MDIM + m0) * KDIM + kk + chunk * 4;
        const unsigned* Bb = gb + ((size_t)r * NDIM + n0) * KDIM + kk + chunk * 4;
        const uint32_t abase = smem_u + (buf * STAGE_WORDS) * 4;
        const uint32_t bbase = abase + TILE_WORDS * 4;
        #pragma unroll
        for (int i = 0; i < 4; i++) {
            const int row = row0 + i * 32;
            cp_async16(abase + (row * SSTRIDE + chunk * 4) * 4, Ab + (size_t)row * KDIM);
            cp_async16(bbase + (row * SSTRIDE + chunk * 4) * 4, Bb + (size_t)row * KDIM);
        }
        CP_COMMIT();
    };

    #pragma unroll
    for (int s = 0; s < STAGES - 1; s++) issue(s, s);

    // per-warp k-step rotation: decorrelates the 16 warps' LDSM bursts and
    // HMMA windows after each barrier (they hit 4 different smem regions and
    // stall at different times -> smoother tensor-pipe occupancy).
    const int krot = warp & 3;

    int buf = 0;
    for (int s = 0; s < TOTAL_STAGES; s++) {
        CP_WAIT(STAGES - 2);
        __syncthreads();   // orders prev iteration's reads before refill below

        if (s + STAGES - 1 < TOTAL_STAGES)
            issue(s + STAGES - 1, (buf + STAGES - 1) % STAGES);
        else
            CP_COMMIT();   // keep group accounting aligned

        const uint32_t tbase = smem_u + (buf * STAGE_WORDS) * 4;

        #pragma unroll
        for (int ksi = 0; ksi < 4; ksi++) {
            const int ks = (ksi + krot) & 3;
            const uint32_t ko = ks * 32;   // 8 words per k8 step
            unsigned af[2][4];
            ldsm_x4(af[0][0], af[0][1], af[0][2], af[0][3], tbase + a_off[0] + ko);
            ldsm_x4(af[1][0], af[1][1], af[1][2], af[1][3], tbase + a_off[1] + ko);
            unsigned bf[4][4];
            #pragma unroll
            for (int p = 0; p < 4; p++)
                ldsm_x4(bf[p][0], bf[p][1], bf[p][2], bf[p][3], tbase + b_off[p] + ko);

            #pragma unroll
            for (int im = 0; im < 2; im++)
                #pragma unroll
                for (int p = 0; p < 4; p++) {
                    mma_tf32_m16n8k8(acc[im][p * 2 + 0], af[im], bf[p][0], bf[p][1]);
                    mma_tf32_m16n8k8(acc[im][p * 2 + 1], af[im], bf[p][2], bf[p][3]);
                }
        }

        if (++buf == STAGES) buf = 0;
    }

    // ---- epilogue ----
    const int m_base = m0 + wm * 32;
    const int n_base = n0 + wn * 64;
    #pragma unroll
    for (int im = 0; im < 2; im++) {
        #pragma unroll
        for (int in = 0; in < 8; in++) {
            int rr = m_base + im * 16 + g;
            int cc = n_base + in * 8 + t * 2;
            *(float2*)(out + (size_t)rr * NDIM + cc) =
                make_float2(acc[im][in][0], acc[im][in][1]);
            *(float2*)(out + (size_t)(rr + 8) * NDIM + cc) =
                make_float2(acc[im][in][2], acc[im][in][3]);
        }
    }
}

// ---------------- host launch ----------------
extern "C" void kernel_launch(void* const* d_in, const int* in_sizes, int n_in,
                              void* d_out, int out_size) {
    const float* a = (const float*)d_in[0];
    const float* b = (const float*)d_in[1];
    float* out = (float*)d_out;

    void *pa = nullptr, *pb = nullptr;
    cudaGetSymbolAddress(&pa, g_a_tf32);
    cudaGetSymbolAddress(&pb, g_b_tf32);

    // pass 1: round both operands to tf32 (RNA) so HMMA truncation is exact
    convert_tf32_kernel<<<2048, 256>>>((const float4*)a, (const float4*)b,
                                       (uint4*)pa, (uint4*)pb);

    // pass 2: pipelined GEMM, rank all-reduce fused into the K loop
    cudaFuncSetAttribute(gemm_ar_tf32_pipe,
                         cudaFuncAttributeMaxDynamicSharedMemorySize, DYN_SMEM);
    const int grid = (MDIM / BM) * (NDIM / BN);   // 1024
    gemm_ar_tf32_pipe<<<grid, NTHREADS, DYN_SMEM>>>(
        (const unsigned*)pa, (const unsigned*)pb, out);
}

// round 14
// speedup vs baseline: 1.9520x; 1.9520x over previous
#include <cuda_runtime.h>
#include <cstdint>

// ---------------- problem constants ----------------
#define WRANKS 8
#define MDIM   4096
#define NDIM   4096
#define KDIM   1792

// ---------------- tile config ----------------
#define BM 128
#define BN 128
#define BK 32
#define NTHREADS 256
#define STAGES 3
#define TOTAL_STAGES ((WRANKS * KDIM) / BK)   // 448
#define STAGES_PER_RANK (KDIM / BK)           // 56

// smem row pitch in words: 36 -> 144B rows; 16B chunks aligned; ldmatrix rows
// stride 4 words mod 32 -> each 8-row matrix tiles all 32 banks (conflict-free)
#define SSTRIDE 36
#define TILE_WORDS (BM * SSTRIDE)             // 4608
#define STAGE_WORDS (2 * TILE_WORDS)
#define DYN_SMEM (STAGES * STAGE_WORDS * 4)   // 110592 B -> 2 CTAs/SM

// ---------------- tf32 scratch (pre-rounded operands) ----------------
__device__ __align__(16) unsigned g_a_tf32[(size_t)WRANKS * MDIM * KDIM];
__device__ __align__(16) unsigned g_b_tf32[(size_t)WRANKS * NDIM * KDIM];

// ---------------- helpers ----------------
__device__ __forceinline__ unsigned f2tf32(float x) {
    unsigned r;
    asm("cvt.rna.tf32.f32 %0, %1;" : "=r"(r) : "f"(x));
    return r;
}

__device__ __forceinline__ uint32_t smem_to_u32(const void* p) {
    uint32_t a;
    asm("{ .reg .u64 t; cvta.to.shared.u64 t, %1; cvt.u32.u64 %0, t; }" : "=r"(a) : "l"(p));
    return a;
}

__device__ __forceinline__ void cp_async16(uint32_t dst, const void* src) {
    asm volatile("cp.async.cg.shared.global [%0], [%1], 16;" :: "r"(dst), "l"(src));
}

// async arrive: fires on this thread's prior cp.async completions; .noinc keeps
// the init count authoritative (init = NTHREADS threads per fill).
__device__ __forceinline__ void cp_async_arrive_noinc(uint32_t bar) {
    asm volatile("cp.async.mbarrier.arrive.noinc.shared.b64 [%0];" :: "r"(bar) : "memory");
}

#define MBARRIER_INIT(addr, cnt) \
    asm volatile("mbarrier.init.shared.b64 [%0], %1;" :: "r"((uint32_t)(addr)), "r"((uint32_t)(cnt)) : "memory")

__device__ __forceinline__ void mbarrier_arrive(uint32_t bar) {
    asm volatile("mbarrier.arrive.release.cta.shared::cta.b64 _, [%0];" :: "r"(bar) : "memory");
}

#define MBARRIER_WAIT_PARITY(addr, parity) do {                                   \
    uint32_t _mbar = (uint32_t)(addr);                                            \
    uint32_t _par  = (uint32_t)(parity);                                          \
    asm volatile(                                                                 \
        "{\n\t"                                                                   \
        ".reg .pred P1;\n\t"                                                      \
        "WAIT_LOOP_%=:\n\t"                                                       \
        "mbarrier.try_wait.parity.acquire.cta.shared::cta.b64 P1, [%0], %1, 0x989680;\n\t" \
        "@P1 bra.uni WAIT_DONE_%=;\n\t"                                           \
        "bra.uni WAIT_LOOP_%=;\n\t"                                               \
        "WAIT_DONE_%=:\n\t"                                                       \
        "}" :: "r"(_mbar), "r"(_par) : "memory");                                 \
} while (0)

// ldmatrix: 4 independent dst regs, canonical mma.sync fragment layout
__device__ __forceinline__ void ldsm_x4(unsigned& r0, unsigned& r1, unsigned& r2, unsigned& r3,
                                        uint32_t addr) {
    asm volatile("ldmatrix.sync.aligned.m8n8.x4.shared.b16 {%0,%1,%2,%3}, [%4];"
                 : "=r"(r0), "=r"(r1), "=r"(r2), "=r"(r3) : "r"(addr));
}

__device__ __forceinline__ void mma_tf32_m16n8k8(float c[4], const unsigned a[4],
                                                 unsigned b0, unsigned b1) {
    asm volatile(
        "mma.sync.aligned.m16n8k8.row.col.f32.tf32.tf32.f32 "
        "{%0,%1,%2,%3}, {%4,%5,%6,%7}, {%8,%9}, {%0,%1,%2,%3};\n"
        : "+f"(c[0]), "+f"(c[1]), "+f"(c[2]), "+f"(c[3])
        : "r"(a[0]), "r"(a[1]), "r"(a[2]), "r"(a[3]), "r"(b0), "r"(b1));
}

// ---------------- pass 1: fp32 -> tf32(RNA) bits ----------------
__global__ void __launch_bounds__(256) convert_tf32_kernel(
    const float4* __restrict__ a, const float4* __restrict__ b,
    uint4* __restrict__ oa, uint4* __restrict__ ob)
{
    const size_t n4 = (size_t)WRANKS * MDIM * KDIM / 4;
    size_t stride = (size_t)gridDim.x * blockDim.x;
    for (size_t i = (size_t)blockIdx.x * blockDim.x + threadIdx.x; i < n4; i += stride) {
        float4 va = a[i];
        uint4 ua = { f2tf32(va.x), f2tf32(va.y), f2tf32(va.z), f2tf32(va.w) };
        oa[i] = ua;
        float4 vb = b[i];
        uint4 ub = { f2tf32(vb.x), f2tf32(vb.y), f2tf32(vb.z), f2tf32(vb.w) };
        ob[i] = ub;
    }
}

// ---------------- pass 2: barrier-free mbarrier-pipelined tf32 GEMM ----------------
extern __shared__ unsigned dsm[];

__global__ void __launch_bounds__(NTHREADS, 2)
gemm_ar_tf32_pipe(const unsigned* __restrict__ ga,   // [W, M, K] tf32 bits
                  const unsigned* __restrict__ gb,   // [W, N, K] tf32 bits
                  float* __restrict__ out)           // [M, N]
{
    __shared__ __align__(8) uint64_t s_full[STAGES];
    __shared__ __align__(8) uint64_t s_empty[STAGES];

    const int tid  = threadIdx.x;
    const int warp = tid >> 5;
    const int lane = tid & 31;
    const int g    = lane >> 2;
    const int t    = lane & 3;

    // grid swizzle: 8-wide N-tile groups (B stays L2-resident across M sweep)
    const int GW = 8;
    const int MT = MDIM / BM;  // 32
    int gid   = blockIdx.x;
    int group = gid / (GW * MT);
    int rem   = gid % (GW * MT);
    int mt    = rem / GW;
    int nt    = group * GW + (rem % GW);
    const int m0 = mt * BM;
    const int n0 = nt * BN;

    const int wm = warp & 3;   // 4x2 warps, each 32(M) x 64(N)
    const int wn = warp >> 2;

    const int row0  = tid >> 3;
    const int chunk = tid & 7;

    const uint32_t smem_u   = smem_to_u32(dsm);
    const uint32_t full_u   = smem_to_u32(&s_full[0]);
    const uint32_t empty_u  = smem_to_u32(&s_empty[0]);

    // ldmatrix per-lane byte offsets (within a tile)
    uint32_t a_off[2], b_off[4];
    {
        const int arow = lane & 15;
        const int acol = (lane >> 4) * 4;
        #pragma unroll
        for (int im = 0; im < 2; im++)
            a_off[im] = ((wm * 32 + im * 16 + arow) * SSTRIDE + acol) * 4;
        const int brow = (lane & 7) + ((lane >> 4) << 3);
        const int bcol = ((lane >> 3) & 1) * 4;
        #pragma unroll
        for (int p = 0; p < 4; p++)
            b_off[p] = ((wn * 64 + p * 16 + brow) * SSTRIDE + bcol) * 4 + TILE_WORDS * 4;
    }

    float acc[2][8][4];
    #pragma unroll
    for (int im = 0; im < 2; im++)
        #pragma unroll
        for (int in = 0; in < 8; in++)
            #pragma unroll
            for (int j = 0; j < 4; j++)
                acc[im][in][j] = 0.0f;

    // init pipeline barriers: full = 256 async (per-thread cp.async completion),
    // empty = 8 (one arrive per warp after consuming a stage)
    if (tid == 0) {
        #pragma unroll
        for (int b = 0; b < STAGES; b++) {
            MBARRIER_INIT(full_u  + b * 8, NTHREADS);
            MBARRIER_INIT(empty_u + b * 8, 8);
        }
    }
    __syncthreads();   // the ONLY block-wide barrier in this kernel

    auto issue = [&](int s, int buf) {
        const int r  = s / STAGES_PER_RANK;
        const int kk = (s % STAGES_PER_RANK) * BK;
        const unsigned* Ab = ga + ((size_t)r * MDIM + m0) * KDIM + kk + chunk * 4;
        const unsigned* Bb = gb + ((size_t)r * NDIM + n0) * KDIM + kk + chunk * 4;
        const uint32_t abase = smem_u + (buf * STAGE_WORDS) * 4;
        const uint32_t bbase = abase + TILE_WORDS * 4;
        #pragma unroll
        for (int i = 0; i < 4; i++) {
            const int row = row0 + i * 32;
            cp_async16(abase + (row * SSTRIDE + chunk * 4) * 4, Ab + (size_t)row * KDIM);
            cp_async16(bbase + (row * SSTRIDE + chunk * 4) * 4, Bb + (size_t)row * KDIM);
        }
        cp_async_arrive_noinc(full_u + buf * 8);   // this thread's fills -> async arrive
    };

    // prologue: fills 0 .. STAGES-2 (no empty wait needed, buffers virgin)
    #pragma unroll
    for (int f = 0; f < STAGES - 1; f++) issue(f, f);

    // cursors: consumer (cb, cph) over full[]; producer (fb, fcyc) over empty[]
    int cb = 0, cph = 0;
    int fb = STAGES - 1, fcyc = 0;

    for (int s = 0; s < TOTAL_STAGES; s++) {
        // wait stage s resident: all 256 threads' cp.asyncs for fill s done
        MBARRIER_WAIT_PARITY(full_u + cb * 8, cph);

        const uint32_t tbase = smem_u + (cb * STAGE_WORDS) * 4;

        #pragma unroll
        for (int ks = 0; ks < 4; ks++) {
            const uint32_t ko = ks * 32;   // 8 words per k8 step
            unsigned af[2][4];
            ldsm_x4(af[0][0], af[0][1], af[0][2], af[0][3], tbase + a_off[0] + ko);
            ldsm_x4(af[1][0], af[1][1], af[1][2], af[1][3], tbase + a_off[1] + ko);
            unsigned bf[4][4];
            #pragma unroll
            for (int p = 0; p < 4; p++)
                ldsm_x4(bf[p][0], bf[p][1], bf[p][2], bf[p][3], tbase + b_off[p] + ko);

            #pragma unroll
            for (int im = 0; im < 2; im++)
                #pragma unroll
                for (int p = 0; p < 4; p++) {
                    mma_tf32_m16n8k8(acc[im][p * 2 + 0], af[im], bf[p][0], bf[p][1]);
                    mma_tf32_m16n8k8(acc[im][p * 2 + 1], af[im], bf[p][2], bf[p][3]);
                }
        }

        // this warp is done reading buffer cb for this cycle
        if (lane == 0) mbarrier_arrive(empty_u + cb * 8);

        // produce fill f = s + STAGES-1 into buffer fb (== (s-1)%3 for s>0)
        const int f = s + STAGES - 1;
        if (f < TOTAL_STAGES) {
            if (fcyc > 0)   // fill f reuses fb: wait all 8 warps consumed fill f-3
                MBARRIER_WAIT_PARITY(empty_u + fb * 8, (fcyc - 1) & 1);
            issue(f, fb);
        }

        if (++cb == STAGES) { cb = 0; cph ^= 1; }
        if (++fb == STAGES) { fb = 0; fcyc++; }
    }

    // ---- epilogue (per-warp independent; no final barrier needed) ----
    const int m_base = m0 + wm * 32;
    const int n_base = n0 + wn * 64;
    #pragma unroll
    for (int im = 0; im < 2; im++) {
        #pragma unroll
        for (int in = 0; in < 8; in++) {
            int rr = m_base + im * 16 + g;
            int cc = n_base + in * 8 + t * 2;
            *(float2*)(out + (size_t)rr * NDIM + cc) =
                make_float2(acc[im][in][0], acc[im][in][1]);
            *(float2*)(out + (size_t)(rr + 8) * NDIM + cc) =
                make_float2(acc[im][in][2], acc[im][in][3]);
        }
    }
}

// ---------------- host launch ----------------
extern "C" void kernel_launch(void* const* d_in, const int* in_sizes, int n_in,
                              void* d_out, int out_size) {
    const float* a = (const float*)d_in[0];
    const float* b = (const float*)d_in[1];
    float* out = (float*)d_out;

    void *pa = nullptr, *pb = nullptr;
    cudaGetSymbolAddress(&pa, g_a_tf32);
    cudaGetSymbolAddress(&pb, g_b_tf32);

    // pass 1: round both operands to tf32 (RNA) so HMMA truncation is exact
    convert_tf32_kernel<<<2048, 256>>>((const float4*)a, (const float4*)b,
                                       (uint4*)pa, (uint4*)pb);

    // pass 2: barrier-free pipelined GEMM, rank all-reduce fused into the K loop
    cudaFuncSetAttribute(gemm_ar_tf32_pipe,
                         cudaFuncAttributeMaxDynamicSharedMemorySize, DYN_SMEM);
    const int grid = (MDIM / BM) * (NDIM / BN);   // 1024
    gemm_ar_tf32_pipe<<<grid, NTHREADS, DYN_SMEM>>>(
        (const unsigned*)pa, (const unsigned*)pb, out);
}